// round 4
// baseline (speedup 1.0000x reference)
#include <cuda_runtime.h>
#include <cuda_fp16.h>
#include <stdint.h>
#include <math.h>

// ---------------------------------------------------------------------------
// EncoderBlock: B=2, N=2048, E=1024, H=16, D=64, FF=4096, fp32 in/out.
// fp16 tensor-core GEMMs (fp32 accum), fused flash attention (128-row q-tiles,
// double-buffered KV), fused epilogues. All scratch in __device__ globals.
// ---------------------------------------------------------------------------

#define TOK    4096      // B*N tokens
#define EMB    1024
#define NHEAD  16
#define HDIM   64
#define FFDIM  4096
#define SEQ    2048
#define QKV3   3072
#define LNEPS  1e-5f
#define SM_SCALE 2.82842712474619f   // 64^0.25  (qk / sqrt(scale), scale=D^-0.5)

// ------------------------------- scratch -----------------------------------
__device__ __half g_xn   [(size_t)TOK * EMB];
__device__ __half g_qkv  [(size_t)TOK * QKV3];
__device__ __half g_wavg [(size_t)TOK * EMB];
__device__ float  g_x2   [(size_t)TOK * EMB];
__device__ __half g_h    [(size_t)TOK * FFDIM];
__device__ __half g_cwqkv[(size_t)EMB * QKV3];
__device__ __half g_cwout[(size_t)EMB * EMB];
__device__ __half g_cw1  [(size_t)EMB * FFDIM];
__device__ __half g_cw2  [(size_t)FFDIM * EMB];

// ------------------------------- helpers -----------------------------------
__device__ __forceinline__ uint32_t smem_u32(const void* p) {
    return (uint32_t)__cvta_generic_to_shared(p);
}
__device__ __forceinline__ void ldsm_x4(uint32_t& r0, uint32_t& r1, uint32_t& r2, uint32_t& r3, uint32_t a) {
    asm volatile("ldmatrix.sync.aligned.m8n8.x4.shared.b16 {%0,%1,%2,%3},[%4];\n"
                 : "=r"(r0), "=r"(r1), "=r"(r2), "=r"(r3) : "r"(a));
}
__device__ __forceinline__ void ldsm_x4_t(uint32_t& r0, uint32_t& r1, uint32_t& r2, uint32_t& r3, uint32_t a) {
    asm volatile("ldmatrix.sync.aligned.m8n8.x4.trans.shared.b16 {%0,%1,%2,%3},[%4];\n"
                 : "=r"(r0), "=r"(r1), "=r"(r2), "=r"(r3) : "r"(a));
}
__device__ __forceinline__ void mma16816(float* c, const uint32_t* a, uint32_t b0, uint32_t b1) {
    asm volatile("mma.sync.aligned.m16n8k16.row.col.f32.f16.f16.f32 "
                 "{%0,%1,%2,%3},{%4,%5,%6,%7},{%8,%9},{%0,%1,%2,%3};\n"
                 : "+f"(c[0]), "+f"(c[1]), "+f"(c[2]), "+f"(c[3])
                 : "r"(a[0]), "r"(a[1]), "r"(a[2]), "r"(a[3]), "r"(b0), "r"(b1));
}
__device__ __forceinline__ void cp_async16(void* s, const void* g) {
    asm volatile("cp.async.cg.shared.global [%0], [%1], 16;\n" :: "r"(smem_u32(s)), "l"(g));
}
__device__ __forceinline__ void cp_commit() { asm volatile("cp.async.commit_group;\n"); }
__device__ __forceinline__ uint32_t f2h2(float a, float b) {
    __half2 h = __floats2half2_rn(a, b);
    return *(uint32_t*)&h;
}
__device__ __forceinline__ float gelu_exact(float x) {
    return 0.5f * x * (1.0f + erff(x * 0.70710678118654752f));
}

// -------------------- fused weight fp32 -> fp16 (one launch) ----------------
__global__ __launch_bounds__(256) void cvt4_kernel(const float* __restrict__ s0,
                                                   const float* __restrict__ s1,
                                                   const float* __restrict__ s2,
                                                   const float* __restrict__ s3,
                                                   __half* __restrict__ d0,
                                                   __half* __restrict__ d1,
                                                   __half* __restrict__ d2,
                                                   __half* __restrict__ d3) {
    const int n0 = EMB * QKV3 / 4;
    const int n1 = EMB * EMB / 4;
    const int n2 = EMB * FFDIM / 4;
    const int n3 = FFDIM * EMB / 4;
    const int ntot = n0 + n1 + n2 + n3;
    for (int i = blockIdx.x * blockDim.x + threadIdx.x; i < ntot; i += gridDim.x * blockDim.x) {
        const float* s; __half* d; int j = i;
        if (j < n0)                { s = s0; d = d0; }
        else if ((j -= n0) < n1)   { s = s1; d = d1; }
        else if ((j -= n1) < n2)   { s = s2; d = d2; }
        else { j -= n2;              s = s3; d = d3; }
        float4 v = ((const float4*)s)[j];
        __half2* o = (__half2*)(d + (size_t)j * 4);
        o[0] = __floats2half2_rn(v.x, v.y);
        o[1] = __floats2half2_rn(v.z, v.w);
    }
}

// ----------------------------- LayerNorm ------------------------------------
__global__ __launch_bounds__(256) void ln_kernel(const float* __restrict__ x,
                                                 const float* __restrict__ g,
                                                 const float* __restrict__ bb,
                                                 __half* __restrict__ out) {
    const int row = blockIdx.x;
    const int tid = threadIdx.x;
    const float4 v = ((const float4*)(x + (size_t)row * EMB))[tid];
    float s1 = v.x + v.y + v.z + v.w;
    float s2 = v.x * v.x + v.y * v.y + v.z * v.z + v.w * v.w;
    __shared__ float sh1[8], sh2[8], stats[2];
    #pragma unroll
    for (int o = 16; o; o >>= 1) {
        s1 += __shfl_xor_sync(0xffffffffu, s1, o);
        s2 += __shfl_xor_sync(0xffffffffu, s2, o);
    }
    if ((tid & 31) == 0) { sh1[tid >> 5] = s1; sh2[tid >> 5] = s2; }
    __syncthreads();
    if (tid == 0) {
        float S = 0.f, Q = 0.f;
        #pragma unroll
        for (int i = 0; i < 8; i++) { S += sh1[i]; Q += sh2[i]; }
        float mu = S * (1.0f / EMB);
        float var = Q * (1.0f / EMB) - mu * mu;
        stats[0] = mu;
        stats[1] = rsqrtf(var + LNEPS);
    }
    __syncthreads();
    const float mu = stats[0], rs = stats[1];
    const int c = tid * 4;
    const float4 gv = ((const float4*)g)[tid];
    const float4 bv = ((const float4*)bb)[tid];
    const float o0 = (v.x - mu) * rs * gv.x + bv.x;
    const float o1 = (v.y - mu) * rs * gv.y + bv.y;
    const float o2 = (v.z - mu) * rs * gv.z + bv.z;
    const float o3 = (v.w - mu) * rs * gv.w + bv.w;
    __half2* op = (__half2*)(out + (size_t)row * EMB + c);
    op[0] = __floats2half2_rn(o0, o1);
    op[1] = __floats2half2_rn(o2, o3);
}

// ------------------------------ GEMM ----------------------------------------
// C[M,N] = A[M,K] @ B[K,N], fp16 in, fp32 accum.
// EPI 0: store half. EPI 1: half(gelu(acc+bias)). EPI 2: float(resid+acc+bias).
template <int EPI>
__global__ __launch_bounds__(256) void gemm_kernel(const __half* __restrict__ A,
                                                   const __half* __restrict__ B,
                                                   const float* __restrict__ bias,
                                                   const float* __restrict__ resid,
                                                   void* __restrict__ Cout,
                                                   int M, int N, int K) {
    __shared__ __align__(16) __half sA[2][128][40];
    __shared__ __align__(16) __half sB[2][32][136];
    const int tid = threadIdx.x, lane = tid & 31, wid = tid >> 5;
    const int bm = blockIdx.y * 128, bn = blockIdx.x * 128;
    const int wm = (wid & 3) * 32, wn = (wid >> 2) * 64;

    float acc[2][8][4];
    #pragma unroll
    for (int mt = 0; mt < 2; mt++)
        #pragma unroll
        for (int nt = 0; nt < 8; nt++)
            #pragma unroll
            for (int i = 0; i < 4; i++) acc[mt][nt][i] = 0.f;

    const int KT = K >> 5;

    auto load_stage = [&](int st, int kt) {
        #pragma unroll
        for (int i = 0; i < 2; i++) {
            int idx = tid + i * 256;
            int ra = idx >> 2, ca = (idx & 3) * 8;
            cp_async16(&sA[st][ra][ca], A + (size_t)(bm + ra) * K + kt * 32 + ca);
            int rb = idx >> 4, cb = (idx & 15) * 8;
            cp_async16(&sB[st][rb][cb], B + (size_t)(kt * 32 + rb) * N + bn + cb);
        }
        cp_commit();
    };

    load_stage(0, 0);
    for (int kt = 0; kt < KT; kt++) {
        if (kt + 1 < KT) {
            load_stage((kt + 1) & 1, kt + 1);
            asm volatile("cp.async.wait_group 1;\n");
        } else {
            asm volatile("cp.async.wait_group 0;\n");
        }
        __syncthreads();
        const int st = kt & 1;
        #pragma unroll
        for (int ks = 0; ks < 2; ks++) {
            uint32_t af[2][4];
            #pragma unroll
            for (int mt = 0; mt < 2; mt++)
                ldsm_x4(af[mt][0], af[mt][1], af[mt][2], af[mt][3],
                        smem_u32(&sA[st][wm + mt * 16 + (lane & 15)][ks * 16 + (lane >> 4) * 8]));
            uint32_t bf[8][2];
            #pragma unroll
            for (int ntp = 0; ntp < 4; ntp++)
                ldsm_x4_t(bf[2 * ntp][0], bf[2 * ntp][1], bf[2 * ntp + 1][0], bf[2 * ntp + 1][1],
                          smem_u32(&sB[st][ks * 16 + (lane & 15)][wn + ntp * 16 + (lane >> 4) * 8]));
            #pragma unroll
            for (int mt = 0; mt < 2; mt++)
                #pragma unroll
                for (int nt = 0; nt < 8; nt++)
                    mma16816(acc[mt][nt], af[mt], bf[nt][0], bf[nt][1]);
        }
        __syncthreads();
    }

    #pragma unroll
    for (int mt = 0; mt < 2; mt++) {
        const int r0 = bm + wm + mt * 16 + (lane >> 2);
        #pragma unroll
        for (int nt = 0; nt < 8; nt++) {
            const int c0 = bn + wn + nt * 8 + 2 * (lane & 3);
            float v0 = acc[mt][nt][0], v1 = acc[mt][nt][1];
            float v2 = acc[mt][nt][2], v3 = acc[mt][nt][3];
            if (EPI == 1 || EPI == 2) {
                const float bb0 = bias[c0], bb1 = bias[c0 + 1];
                v0 += bb0; v1 += bb1; v2 += bb0; v3 += bb1;
            }
            if (EPI == 1) {
                v0 = gelu_exact(v0); v1 = gelu_exact(v1);
                v2 = gelu_exact(v2); v3 = gelu_exact(v3);
            }
            const size_t i0 = (size_t)r0 * N + c0;
            const size_t i1 = (size_t)(r0 + 8) * N + c0;
            if (EPI == 2) {
                float* C = (float*)Cout;
                float2 o0 = make_float2(resid[i0] + v0, resid[i0 + 1] + v1);
                float2 o1 = make_float2(resid[i1] + v2, resid[i1 + 1] + v3);
                *(float2*)(C + i0) = o0;
                *(float2*)(C + i1) = o1;
            } else {
                __half* C = (__half*)Cout;
                *(__half2*)(C + i0) = __floats2half2_rn(v0, v1);
                *(__half2*)(C + i1) = __floats2half2_rn(v2, v3);
            }
        }
    }
}

// --------------------------- Flash attention --------------------------------
// grid: (SEQ/128, B*H), 256 threads (8 warps, 16 q-rows each).
// KV tiles (64 rows) double-buffered via cp.async; sQ overlaid on KV buffers.
__global__ __launch_bounds__(256) void flash_kernel() {
    const int bh = blockIdx.y;
    const int b = bh >> 4, h = bh & 15;
    const int q0 = blockIdx.x * 128;
    const int tid = threadIdx.x, lane = tid & 31, wid = tid >> 5;

    // sbuf[0..1] = K stages, sbuf[2..3] = V stages; prologue: rows 0..127 = Q
    __shared__ __align__(16) __half sbuf[4][64][72];

    // ---- Q prologue (uses sbuf as [128][72]) ----
    {
        __half (*sQ)[72] = (__half(*)[72])sbuf;
        const __half* qbase = g_qkv + (size_t)(b * SEQ + q0) * QKV3 + h * HDIM;
        #pragma unroll
        for (int i = 0; i < 4; i++) {
            int idx = tid + 256 * i;      // 0..1023 : 128 rows x 8 chunks
            int r = idx >> 3, c = (idx & 7) * 8;
            *(uint4*)&sQ[r][c] = *(const uint4*)(qbase + (size_t)r * QKV3 + c);
        }
    }
    __syncthreads();

    uint32_t qf[4][4];
    {
        __half (*sQ)[72] = (__half(*)[72])sbuf;
        const int rr = wid * 16 + (lane & 15);
        const int cc = (lane >> 4) * 8;
        #pragma unroll
        for (int kk = 0; kk < 4; kk++)
            ldsm_x4(qf[kk][0], qf[kk][1], qf[kk][2], qf[kk][3],
                    smem_u32(&sQ[rr][kk * 16 + cc]));
    }
    __syncthreads();   // everyone has qf; safe to overwrite sbuf with KV

    float m_lo = -1e30f, m_hi = -1e30f, l_lo = 0.f, l_hi = 0.f;
    float O[8][4];
    #pragma unroll
    for (int nt = 0; nt < 8; nt++)
        #pragma unroll
        for (int i = 0; i < 4; i++) O[nt][i] = 0.f;

    const __half* kbase = g_qkv + (size_t)(b * SEQ) * QKV3 + EMB + h * HDIM;
    const __half* vbase = kbase + EMB;

    auto load_kv = [&](int st, int kv0) {
        const __half* kb = kbase + (size_t)kv0 * QKV3;
        const __half* vb = vbase + (size_t)kv0 * QKV3;
        #pragma unroll
        for (int i = 0; i < 2; i++) {
            int idx = tid + 256 * i;      // 0..511 : 64 rows x 8 chunks
            int r = idx >> 3, c = (idx & 7) * 8;
            cp_async16(&sbuf[st][r][c],     kb + (size_t)r * QKV3 + c);
            cp_async16(&sbuf[2 + st][r][c], vb + (size_t)r * QKV3 + c);
        }
        cp_commit();
    };

    load_kv(0, 0);
    const int NIT = SEQ / 64;
    for (int it = 0; it < NIT; it++) {
        if (it + 1 < NIT) {
            load_kv((it + 1) & 1, (it + 1) * 64);
            asm volatile("cp.async.wait_group 1;\n");
        } else {
            asm volatile("cp.async.wait_group 0;\n");
        }
        __syncthreads();
        const int st = it & 1;

        // S = Q @ K^T (per warp: 16 x 64)
        float S[8][4];
        #pragma unroll
        for (int nt = 0; nt < 8; nt++)
            #pragma unroll
            for (int i = 0; i < 4; i++) S[nt][i] = 0.f;
        #pragma unroll
        for (int kk = 0; kk < 4; kk++) {
            const int dcol = kk * 16 + ((lane >> 3) & 1) * 8;
            #pragma unroll
            for (int ntp = 0; ntp < 4; ntp++) {
                const int jrow = ntp * 16 + ((lane >> 4) << 3) + (lane & 7);
                uint32_t b0, b1, b2, b3;
                ldsm_x4(b0, b1, b2, b3, smem_u32(&sbuf[st][jrow][dcol]));
                mma16816(S[2 * ntp], qf[kk], b0, b1);
                mma16816(S[2 * ntp + 1], qf[kk], b2, b3);
            }
        }

        // online softmax (rows lane>>2 and lane>>2 + 8)
        float mx_lo = -1e30f, mx_hi = -1e30f;
        #pragma unroll
        for (int nt = 0; nt < 8; nt++) {
            S[nt][0] *= SM_SCALE; S[nt][1] *= SM_SCALE;
            S[nt][2] *= SM_SCALE; S[nt][3] *= SM_SCALE;
            mx_lo = fmaxf(mx_lo, fmaxf(S[nt][0], S[nt][1]));
            mx_hi = fmaxf(mx_hi, fmaxf(S[nt][2], S[nt][3]));
        }
        mx_lo = fmaxf(mx_lo, __shfl_xor_sync(0xffffffffu, mx_lo, 1));
        mx_lo = fmaxf(mx_lo, __shfl_xor_sync(0xffffffffu, mx_lo, 2));
        mx_hi = fmaxf(mx_hi, __shfl_xor_sync(0xffffffffu, mx_hi, 1));
        mx_hi = fmaxf(mx_hi, __shfl_xor_sync(0xffffffffu, mx_hi, 2));
        const float mn_lo = fmaxf(m_lo, mx_lo);
        const float mn_hi = fmaxf(m_hi, mx_hi);
        const float fac_lo = __expf(m_lo - mn_lo);
        const float fac_hi = __expf(m_hi - mn_hi);
        float sum_lo = 0.f, sum_hi = 0.f;
        #pragma unroll
        for (int nt = 0; nt < 8; nt++) {
            S[nt][0] = __expf(S[nt][0] - mn_lo);
            S[nt][1] = __expf(S[nt][1] - mn_lo);
            S[nt][2] = __expf(S[nt][2] - mn_hi);
            S[nt][3] = __expf(S[nt][3] - mn_hi);
            sum_lo += S[nt][0] + S[nt][1];
            sum_hi += S[nt][2] + S[nt][3];
        }
        sum_lo += __shfl_xor_sync(0xffffffffu, sum_lo, 1);
        sum_lo += __shfl_xor_sync(0xffffffffu, sum_lo, 2);
        sum_hi += __shfl_xor_sync(0xffffffffu, sum_hi, 1);
        sum_hi += __shfl_xor_sync(0xffffffffu, sum_hi, 2);
        l_lo = l_lo * fac_lo + sum_lo;
        l_hi = l_hi * fac_hi + sum_hi;
        #pragma unroll
        for (int nt = 0; nt < 8; nt++) {
            O[nt][0] *= fac_lo; O[nt][1] *= fac_lo;
            O[nt][2] *= fac_hi; O[nt][3] *= fac_hi;
        }
        m_lo = mn_lo; m_hi = mn_hi;

        // O += P @ V
        #pragma unroll
        for (int kj = 0; kj < 4; kj++) {
            uint32_t a[4];
            a[0] = f2h2(S[2 * kj][0],     S[2 * kj][1]);
            a[1] = f2h2(S[2 * kj][2],     S[2 * kj][3]);
            a[2] = f2h2(S[2 * kj + 1][0], S[2 * kj + 1][1]);
            a[3] = f2h2(S[2 * kj + 1][2], S[2 * kj + 1][3]);
            const int vrow = kj * 16 + (lane & 15);
            #pragma unroll
            for (int ntp = 0; ntp < 4; ntp++) {
                const int vcol = ntp * 16 + (lane >> 4) * 8;
                uint32_t b0, b1, b2, b3;
                ldsm_x4_t(b0, b1, b2, b3, smem_u32(&sbuf[2 + st][vrow][vcol]));
                mma16816(O[2 * ntp],     a, b0, b1);
                mma16816(O[2 * ntp + 1], a, b2, b3);
            }
        }
        __syncthreads();
    }

    // normalize + store
    const float inv_lo = 1.0f / l_lo;
    const float inv_hi = 1.0f / l_hi;
    const int r = q0 + wid * 16 + (lane >> 2);
    __half* outp = g_wavg + (size_t)(b * SEQ) * EMB + h * HDIM;
    #pragma unroll
    for (int nt = 0; nt < 8; nt++) {
        const int col = nt * 8 + 2 * (lane & 3);
        *(__half2*)(outp + (size_t)r * EMB + col) =
            __floats2half2_rn(O[nt][0] * inv_lo, O[nt][1] * inv_lo);
        *(__half2*)(outp + (size_t)(r + 8) * EMB + col) =
            __floats2half2_rn(O[nt][2] * inv_hi, O[nt][3] * inv_hi);
    }
}

// ------------------------------- launch -------------------------------------
extern "C" void kernel_launch(void* const* d_in, const int* in_sizes, int n_in,
                              void* d_out, int out_size) {
    const float* x     = (const float*)d_in[0];
    const float* w_qkv = (const float*)d_in[1];
    const float* w_out = (const float*)d_in[2];
    const float* b_out = (const float*)d_in[3];
    const float* ln1_g = (const float*)d_in[4];
    const float* ln1_b = (const float*)d_in[5];
    const float* ln2_g = (const float*)d_in[6];
    const float* ln2_b = (const float*)d_in[7];
    const float* w1    = (const float*)d_in[8];
    const float* b1    = (const float*)d_in[9];
    const float* w2    = (const float*)d_in[10];
    const float* b2    = (const float*)d_in[11];

    void *p_xn, *p_qkv, *p_wavg, *p_x2, *p_h, *p_cwqkv, *p_cwout, *p_cw1, *p_cw2;
    cudaGetSymbolAddress(&p_xn, g_xn);
    cudaGetSymbolAddress(&p_qkv, g_qkv);
    cudaGetSymbolAddress(&p_wavg, g_wavg);
    cudaGetSymbolAddress(&p_x2, g_x2);
    cudaGetSymbolAddress(&p_h, g_h);
    cudaGetSymbolAddress(&p_cwqkv, g_cwqkv);
    cudaGetSymbolAddress(&p_cwout, g_cwout);
    cudaGetSymbolAddress(&p_cw1, g_cw1);
    cudaGetSymbolAddress(&p_cw2, g_cw2);

    // 0: all weight conversions fused
    cvt4_kernel<<<1024, 256>>>(w_qkv, w_out, w1, w2,
                               (__half*)p_cwqkv, (__half*)p_cwout,
                               (__half*)p_cw1, (__half*)p_cw2);
    // 1: LN1
    ln_kernel<<<TOK, 256>>>(x, ln1_g, ln1_b, (__half*)p_xn);
    // 2: QKV projection
    gemm_kernel<0><<<dim3(QKV3 / 128, TOK / 128), 256>>>(
        (const __half*)p_xn, (const __half*)p_cwqkv, nullptr, nullptr, p_qkv, TOK, QKV3, EMB);
    // 3: fused attention
    flash_kernel<<<dim3(SEQ / 128, 2 * NHEAD), 256>>>();
    // 4: out projection + bias + residual(x)   <-- ncu -s 5 lands here
    gemm_kernel<2><<<dim3(EMB / 128, TOK / 128), 256>>>(
        (const __half*)p_wavg, (const __half*)p_cwout, b_out, x, p_x2, TOK, EMB, EMB);
    // 5: LN2
    ln_kernel<<<TOK, 256>>>((const float*)p_x2, ln2_g, ln2_b, (__half*)p_xn);
    // 6: FF1 + bias + gelu
    gemm_kernel<1><<<dim3(FFDIM / 128, TOK / 128), 256>>>(
        (const __half*)p_xn, (const __half*)p_cw1, b1, nullptr, p_h, TOK, FFDIM, EMB);
    // 7: FF2 + bias + residual
    gemm_kernel<2><<<dim3(EMB / 128, TOK / 128), 256>>>(
        (const __half*)p_h, (const __half*)p_cw2, b2, (const float*)p_x2, d_out, TOK, EMB, FFDIM);
}

// round 8
// speedup vs baseline: 1.0285x; 1.0285x over previous
#include <cuda_runtime.h>
#include <cuda_fp16.h>
#include <stdint.h>
#include <math.h>

// ---------------------------------------------------------------------------
// EncoderBlock: B=2, N=2048, E=1024, H=16, D=64, FF=4096, fp32 in/out.
// R8: 4-stage cp.async GEMM pipeline with FIXED tail (one commit-group per
// iteration, empty commits in tail -> wait_group 2 provably covers stage kt).
// Flash softmax on exp2 with folded scale. Plain sm_100 features only.
// ---------------------------------------------------------------------------

#define TOK    4096
#define EMB    1024
#define NHEAD  16
#define HDIM   64
#define FFDIM  4096
#define SEQ    2048
#define QKV3   3072
#define LNEPS  1e-5f
#define SM_SCALE 2.82842712474619f   // 64^0.25  (qk / sqrt(scale), scale=D^-0.5)
#define SM_C    (2.82842712474619f * 1.44269504088896f)   // SM_SCALE * log2(e)

// ------------------------------- scratch -----------------------------------
__device__ __half g_xn   [(size_t)TOK * EMB];
__device__ __half g_qkv  [(size_t)TOK * QKV3];
__device__ __half g_wavg [(size_t)TOK * EMB];
__device__ float  g_x2   [(size_t)TOK * EMB];
__device__ __half g_h    [(size_t)TOK * FFDIM];
__device__ __half g_cwqkv[(size_t)EMB * QKV3];
__device__ __half g_cwout[(size_t)EMB * EMB];
__device__ __half g_cw1  [(size_t)EMB * FFDIM];
__device__ __half g_cw2  [(size_t)FFDIM * EMB];

// ------------------------------- helpers -----------------------------------
__device__ __forceinline__ uint32_t smem_u32(const void* p) {
    return (uint32_t)__cvta_generic_to_shared(p);
}
__device__ __forceinline__ void ldsm_x4(uint32_t& r0, uint32_t& r1, uint32_t& r2, uint32_t& r3, uint32_t a) {
    asm volatile("ldmatrix.sync.aligned.m8n8.x4.shared.b16 {%0,%1,%2,%3},[%4];\n"
                 : "=r"(r0), "=r"(r1), "=r"(r2), "=r"(r3) : "r"(a));
}
__device__ __forceinline__ void ldsm_x4_t(uint32_t& r0, uint32_t& r1, uint32_t& r2, uint32_t& r3, uint32_t a) {
    asm volatile("ldmatrix.sync.aligned.m8n8.x4.trans.shared.b16 {%0,%1,%2,%3},[%4];\n"
                 : "=r"(r0), "=r"(r1), "=r"(r2), "=r"(r3) : "r"(a));
}
__device__ __forceinline__ void mma16816(float* c, const uint32_t* a, uint32_t b0, uint32_t b1) {
    asm volatile("mma.sync.aligned.m16n8k16.row.col.f32.f16.f16.f32 "
                 "{%0,%1,%2,%3},{%4,%5,%6,%7},{%8,%9},{%0,%1,%2,%3};\n"
                 : "+f"(c[0]), "+f"(c[1]), "+f"(c[2]), "+f"(c[3])
                 : "r"(a[0]), "r"(a[1]), "r"(a[2]), "r"(a[3]), "r"(b0), "r"(b1));
}
__device__ __forceinline__ void cp_async16(void* s, const void* g) {
    asm volatile("cp.async.cg.shared.global [%0], [%1], 16;\n" :: "r"(smem_u32(s)), "l"(g));
}
__device__ __forceinline__ void cp_commit() { asm volatile("cp.async.commit_group;\n"); }
__device__ __forceinline__ uint32_t f2h2(float a, float b) {
    __half2 h = __floats2half2_rn(a, b);
    return *(uint32_t*)&h;
}
__device__ __forceinline__ float gelu_exact(float x) {
    return 0.5f * x * (1.0f + erff(x * 0.70710678118654752f));
}

// -------------------- fused weight fp32 -> fp16 (one launch) ----------------
__global__ __launch_bounds__(256) void cvt4_kernel(const float* __restrict__ s0,
                                                   const float* __restrict__ s1,
                                                   const float* __restrict__ s2,
                                                   const float* __restrict__ s3,
                                                   __half* __restrict__ d0,
                                                   __half* __restrict__ d1,
                                                   __half* __restrict__ d2,
                                                   __half* __restrict__ d3) {
    const int n0 = EMB * QKV3 / 4;
    const int n1 = EMB * EMB / 4;
    const int n2 = EMB * FFDIM / 4;
    const int n3 = FFDIM * EMB / 4;
    const int ntot = n0 + n1 + n2 + n3;
    for (int i = blockIdx.x * blockDim.x + threadIdx.x; i < ntot; i += gridDim.x * blockDim.x) {
        const float* s; __half* d; int j = i;
        if (j < n0)                { s = s0; d = d0; }
        else if ((j -= n0) < n1)   { s = s1; d = d1; }
        else if ((j -= n1) < n2)   { s = s2; d = d2; }
        else { j -= n2;              s = s3; d = d3; }
        float4 v = ((const float4*)s)[j];
        __half2* o = (__half2*)(d + (size_t)j * 4);
        o[0] = __floats2half2_rn(v.x, v.y);
        o[1] = __floats2half2_rn(v.z, v.w);
    }
}

// ----------------------------- LayerNorm ------------------------------------
__global__ __launch_bounds__(256) void ln_kernel(const float* __restrict__ x,
                                                 const float* __restrict__ g,
                                                 const float* __restrict__ bb,
                                                 __half* __restrict__ out) {
    const int row = blockIdx.x;
    const int tid = threadIdx.x;
    const float4 v = ((const float4*)(x + (size_t)row * EMB))[tid];
    float s1 = v.x + v.y + v.z + v.w;
    float s2 = v.x * v.x + v.y * v.y + v.z * v.z + v.w * v.w;
    __shared__ float sh1[8], sh2[8], stats[2];
    #pragma unroll
    for (int o = 16; o; o >>= 1) {
        s1 += __shfl_xor_sync(0xffffffffu, s1, o);
        s2 += __shfl_xor_sync(0xffffffffu, s2, o);
    }
    if ((tid & 31) == 0) { sh1[tid >> 5] = s1; sh2[tid >> 5] = s2; }
    __syncthreads();
    if (tid == 0) {
        float S = 0.f, Q = 0.f;
        #pragma unroll
        for (int i = 0; i < 8; i++) { S += sh1[i]; Q += sh2[i]; }
        float mu = S * (1.0f / EMB);
        float var = Q * (1.0f / EMB) - mu * mu;
        stats[0] = mu;
        stats[1] = rsqrtf(var + LNEPS);
    }
    __syncthreads();
    const float mu = stats[0], rs = stats[1];
    const int c = tid * 4;
    const float4 gv = ((const float4*)g)[tid];
    const float4 bv = ((const float4*)bb)[tid];
    const float o0 = (v.x - mu) * rs * gv.x + bv.x;
    const float o1 = (v.y - mu) * rs * gv.y + bv.y;
    const float o2 = (v.z - mu) * rs * gv.z + bv.z;
    const float o3 = (v.w - mu) * rs * gv.w + bv.w;
    __half2* op = (__half2*)(out + (size_t)row * EMB + c);
    op[0] = __floats2half2_rn(o0, o1);
    op[1] = __floats2half2_rn(o2, o3);
}

// ------------------------------ GEMM ----------------------------------------
// C[M,N] = A[M,K] @ B[K,N], fp16 in, fp32 accum. 4-stage cp.async pipeline,
// one commit-group PER ITERATION (empty in tail) so wait_group 2 always
// guarantees stage kt residency. One __syncthreads per BK=32 iteration.
struct GemmSmem {
    __half A[4][128][40];
    __half B[4][32][136];
};
template <int EPI>
__global__ __launch_bounds__(256) void gemm_kernel(const __half* __restrict__ Ag,
                                                   const __half* __restrict__ Bg,
                                                   const float* __restrict__ bias,
                                                   const float* __restrict__ resid,
                                                   void* __restrict__ Cout,
                                                   int M, int N, int K) {
    extern __shared__ __align__(16) char smem_raw[];
    GemmSmem& sm = *(GemmSmem*)smem_raw;
    const int tid = threadIdx.x, lane = tid & 31, wid = tid >> 5;
    const int bm = blockIdx.y * 128, bn = blockIdx.x * 128;
    const int wm = (wid & 3) * 32, wn = (wid >> 2) * 64;

    float acc[2][8][4];
    #pragma unroll
    for (int mt = 0; mt < 2; mt++)
        #pragma unroll
        for (int nt = 0; nt < 8; nt++)
            #pragma unroll
            for (int i = 0; i < 4; i++) acc[mt][nt][i] = 0.f;

    const int KT = K >> 5;

    auto load_stage = [&](int st, int kt) {
        #pragma unroll
        for (int i = 0; i < 2; i++) {
            int idx = tid + i * 256;
            int ra = idx >> 2, ca = (idx & 3) * 8;
            cp_async16(&sm.A[st][ra][ca], Ag + (size_t)(bm + ra) * K + kt * 32 + ca);
            int rb = idx >> 4, cb = (idx & 15) * 8;
            cp_async16(&sm.B[st][rb][cb], Bg + (size_t)(kt * 32 + rb) * N + bn + cb);
        }
        cp_commit();
    };

    // prologue: fill 3 of 4 stages (3 commit groups)
    load_stage(0, 0);
    load_stage(1, 1);
    load_stage(2, 2);

    for (int kt = 0; kt < KT; kt++) {
        // commits so far = 3 + kt; the 2 newest cover stages kt+1, kt+2,
        // so wait_group 2 retires through stage kt. Invariant holds because
        // EVERY iteration below commits exactly one group (real or empty).
        asm volatile("cp.async.wait_group 2;\n");
        __syncthreads();                 // all warps done with stage (kt-1)&3
        if (kt + 3 < KT) load_stage((kt + 3) & 3, kt + 3);
        else             cp_commit();    // empty group keeps the count aligned
        const int st = kt & 3;
        #pragma unroll
        for (int ks = 0; ks < 2; ks++) {
            uint32_t af[2][4];
            #pragma unroll
            for (int mt = 0; mt < 2; mt++)
                ldsm_x4(af[mt][0], af[mt][1], af[mt][2], af[mt][3],
                        smem_u32(&sm.A[st][wm + mt * 16 + (lane & 15)][ks * 16 + (lane >> 4) * 8]));
            uint32_t bf[8][2];
            #pragma unroll
            for (int ntp = 0; ntp < 4; ntp++)
                ldsm_x4_t(bf[2 * ntp][0], bf[2 * ntp][1], bf[2 * ntp + 1][0], bf[2 * ntp + 1][1],
                          smem_u32(&sm.B[st][ks * 16 + (lane & 15)][wn + ntp * 16 + (lane >> 4) * 8]));
            #pragma unroll
            for (int mt = 0; mt < 2; mt++)
                #pragma unroll
                for (int nt = 0; nt < 8; nt++)
                    mma16816(acc[mt][nt], af[mt], bf[nt][0], bf[nt][1]);
        }
    }

    #pragma unroll
    for (int mt = 0; mt < 2; mt++) {
        const int r0 = bm + wm + mt * 16 + (lane >> 2);
        #pragma unroll
        for (int nt = 0; nt < 8; nt++) {
            const int c0 = bn + wn + nt * 8 + 2 * (lane & 3);
            float v0 = acc[mt][nt][0], v1 = acc[mt][nt][1];
            float v2 = acc[mt][nt][2], v3 = acc[mt][nt][3];
            if (EPI == 1 || EPI == 2) {
                const float bb0 = bias[c0], bb1 = bias[c0 + 1];
                v0 += bb0; v1 += bb1; v2 += bb0; v3 += bb1;
            }
            if (EPI == 1) {
                v0 = gelu_exact(v0); v1 = gelu_exact(v1);
                v2 = gelu_exact(v2); v3 = gelu_exact(v3);
            }
            const size_t i0 = (size_t)r0 * N + c0;
            const size_t i1 = (size_t)(r0 + 8) * N + c0;
            if (EPI == 2) {
                float* C = (float*)Cout;
                float2 o0 = make_float2(resid[i0] + v0, resid[i0 + 1] + v1);
                float2 o1 = make_float2(resid[i1] + v2, resid[i1 + 1] + v3);
                *(float2*)(C + i0) = o0;
                *(float2*)(C + i1) = o1;
            } else {
                __half* C = (__half*)Cout;
                *(__half2*)(C + i0) = __floats2half2_rn(v0, v1);
                *(__half2*)(C + i1) = __floats2half2_rn(v2, v3);
            }
        }
    }
}

// --------------------------- Flash attention --------------------------------
// grid: (SEQ/128, B*H), 256 threads (8 warps, 16 q-rows each).
// Softmax in exp2 domain with SM_SCALE folded in (raw-domain max; C > 0).
__global__ __launch_bounds__(256) void flash_kernel() {
    const int bh = blockIdx.y;
    const int b = bh >> 4, h = bh & 15;
    const int q0 = blockIdx.x * 128;
    const int tid = threadIdx.x, lane = tid & 31, wid = tid >> 5;

    __shared__ __align__(16) __half sbuf[4][64][72];

    {
        __half (*sQ)[72] = (__half(*)[72])sbuf;
        const __half* qbase = g_qkv + (size_t)(b * SEQ + q0) * QKV3 + h * HDIM;
        #pragma unroll
        for (int i = 0; i < 4; i++) {
            int idx = tid + 256 * i;
            int r = idx >> 3, c = (idx & 7) * 8;
            *(uint4*)&sQ[r][c] = *(const uint4*)(qbase + (size_t)r * QKV3 + c);
        }
    }
    __syncthreads();

    uint32_t qf[4][4];
    {
        __half (*sQ)[72] = (__half(*)[72])sbuf;
        const int rr = wid * 16 + (lane & 15);
        const int cc = (lane >> 4) * 8;
        #pragma unroll
        for (int kk = 0; kk < 4; kk++)
            ldsm_x4(qf[kk][0], qf[kk][1], qf[kk][2], qf[kk][3],
                    smem_u32(&sQ[rr][kk * 16 + cc]));
    }
    __syncthreads();

    float m_lo = -1e30f, m_hi = -1e30f, l_lo = 0.f, l_hi = 0.f;   // raw-domain maxima
    float O[8][4];
    #pragma unroll
    for (int nt = 0; nt < 8; nt++)
        #pragma unroll
        for (int i = 0; i < 4; i++) O[nt][i] = 0.f;

    const __half* kbase = g_qkv + (size_t)(b * SEQ) * QKV3 + EMB + h * HDIM;
    const __half* vbase = kbase + EMB;

    auto load_kv = [&](int st, int kv0) {
        const __half* kb = kbase + (size_t)kv0 * QKV3;
        const __half* vb = vbase + (size_t)kv0 * QKV3;
        #pragma unroll
        for (int i = 0; i < 2; i++) {
            int idx = tid + 256 * i;
            int r = idx >> 3, c = (idx & 7) * 8;
            cp_async16(&sbuf[st][r][c],     kb + (size_t)r * QKV3 + c);
            cp_async16(&sbuf[2 + st][r][c], vb + (size_t)r * QKV3 + c);
        }
        cp_commit();
    };

    load_kv(0, 0);
    const int NIT = SEQ / 64;
    for (int it = 0; it < NIT; it++) {
        if (it + 1 < NIT) {
            load_kv((it + 1) & 1, (it + 1) * 64);
            asm volatile("cp.async.wait_group 1;\n");
        } else {
            asm volatile("cp.async.wait_group 0;\n");
        }
        __syncthreads();
        const int st = it & 1;

        float S[8][4];
        #pragma unroll
        for (int nt = 0; nt < 8; nt++)
            #pragma unroll
            for (int i = 0; i < 4; i++) S[nt][i] = 0.f;
        #pragma unroll
        for (int kk = 0; kk < 4; kk++) {
            const int dcol = kk * 16 + ((lane >> 3) & 1) * 8;
            #pragma unroll
            for (int ntp = 0; ntp < 4; ntp++) {
                const int jrow = ntp * 16 + ((lane >> 4) << 3) + (lane & 7);
                uint32_t b0, b1, b2, b3;
                ldsm_x4(b0, b1, b2, b3, smem_u32(&sbuf[st][jrow][dcol]));
                mma16816(S[2 * ntp], qf[kk], b0, b1);
                mma16816(S[2 * ntp + 1], qf[kk], b2, b3);
            }
        }

        // online softmax (raw-domain max; exp2 with folded scale)
        float mx_lo = -1e30f, mx_hi = -1e30f;
        #pragma unroll
        for (int nt = 0; nt < 8; nt++) {
            mx_lo = fmaxf(mx_lo, fmaxf(S[nt][0], S[nt][1]));
            mx_hi = fmaxf(mx_hi, fmaxf(S[nt][2], S[nt][3]));
        }
        mx_lo = fmaxf(mx_lo, __shfl_xor_sync(0xffffffffu, mx_lo, 1));
        mx_lo = fmaxf(mx_lo, __shfl_xor_sync(0xffffffffu, mx_lo, 2));
        mx_hi = fmaxf(mx_hi, __shfl_xor_sync(0xffffffffu, mx_hi, 1));
        mx_hi = fmaxf(mx_hi, __shfl_xor_sync(0xffffffffu, mx_hi, 2));
        const float mn_lo = fmaxf(m_lo, mx_lo);
        const float mn_hi = fmaxf(m_hi, mx_hi);
        const float fac_lo = exp2f((m_lo - mn_lo) * SM_C);
        const float fac_hi = exp2f((m_hi - mn_hi) * SM_C);
        const float off_lo = mn_lo * SM_C;
        const float off_hi = mn_hi * SM_C;
        float sum_lo = 0.f, sum_hi = 0.f;
        #pragma unroll
        for (int nt = 0; nt < 8; nt++) {
            S[nt][0] = exp2f(fmaf(S[nt][0], SM_C, -off_lo));
            S[nt][1] = exp2f(fmaf(S[nt][1], SM_C, -off_lo));
            S[nt][2] = exp2f(fmaf(S[nt][2], SM_C, -off_hi));
            S[nt][3] = exp2f(fmaf(S[nt][3], SM_C, -off_hi));
            sum_lo += S[nt][0] + S[nt][1];
            sum_hi += S[nt][2] + S[nt][3];
        }
        sum_lo += __shfl_xor_sync(0xffffffffu, sum_lo, 1);
        sum_lo += __shfl_xor_sync(0xffffffffu, sum_lo, 2);
        sum_hi += __shfl_xor_sync(0xffffffffu, sum_hi, 1);
        sum_hi += __shfl_xor_sync(0xffffffffu, sum_hi, 2);
        l_lo = l_lo * fac_lo + sum_lo;
        l_hi = l_hi * fac_hi + sum_hi;
        #pragma unroll
        for (int nt = 0; nt < 8; nt++) {
            O[nt][0] *= fac_lo; O[nt][1] *= fac_lo;
            O[nt][2] *= fac_hi; O[nt][3] *= fac_hi;
        }
        m_lo = mn_lo; m_hi = mn_hi;

        #pragma unroll
        for (int kj = 0; kj < 4; kj++) {
            uint32_t a[4];
            a[0] = f2h2(S[2 * kj][0],     S[2 * kj][1]);
            a[1] = f2h2(S[2 * kj][2],     S[2 * kj][3]);
            a[2] = f2h2(S[2 * kj + 1][0], S[2 * kj + 1][1]);
            a[3] = f2h2(S[2 * kj + 1][2], S[2 * kj + 1][3]);
            const int vrow = kj * 16 + (lane & 15);
            #pragma unroll
            for (int ntp = 0; ntp < 4; ntp++) {
                const int vcol = ntp * 16 + (lane >> 4) * 8;
                uint32_t b0, b1, b2, b3;
                ldsm_x4_t(b0, b1, b2, b3, smem_u32(&sbuf[2 + st][vrow][vcol]));
                mma16816(O[2 * ntp],     a, b0, b1);
                mma16816(O[2 * ntp + 1], a, b2, b3);
            }
        }
        __syncthreads();
    }

    const float inv_lo = 1.0f / l_lo;
    const float inv_hi = 1.0f / l_hi;
    const int r = q0 + wid * 16 + (lane >> 2);
    __half* outp = g_wavg + (size_t)(b * SEQ) * EMB + h * HDIM;
    #pragma unroll
    for (int nt = 0; nt < 8; nt++) {
        const int col = nt * 8 + 2 * (lane & 3);
        *(__half2*)(outp + (size_t)r * EMB + col) =
            __floats2half2_rn(O[nt][0] * inv_lo, O[nt][1] * inv_lo);
        *(__half2*)(outp + (size_t)(r + 8) * EMB + col) =
            __floats2half2_rn(O[nt][2] * inv_hi, O[nt][3] * inv_hi);
    }
}

// ------------------------------- launch -------------------------------------
extern "C" void kernel_launch(void* const* d_in, const int* in_sizes, int n_in,
                              void* d_out, int out_size) {
    const float* x     = (const float*)d_in[0];
    const float* w_qkv = (const float*)d_in[1];
    const float* w_out = (const float*)d_in[2];
    const float* b_out = (const float*)d_in[3];
    const float* ln1_g = (const float*)d_in[4];
    const float* ln1_b = (const float*)d_in[5];
    const float* ln2_g = (const float*)d_in[6];
    const float* ln2_b = (const float*)d_in[7];
    const float* w1    = (const float*)d_in[8];
    const float* b1    = (const float*)d_in[9];
    const float* w2    = (const float*)d_in[10];
    const float* b2    = (const float*)d_in[11];

    void *p_xn, *p_qkv, *p_wavg, *p_x2, *p_h, *p_cwqkv, *p_cwout, *p_cw1, *p_cw2;
    cudaGetSymbolAddress(&p_xn, g_xn);
    cudaGetSymbolAddress(&p_qkv, g_qkv);
    cudaGetSymbolAddress(&p_wavg, g_wavg);
    cudaGetSymbolAddress(&p_x2, g_x2);
    cudaGetSymbolAddress(&p_h, g_h);
    cudaGetSymbolAddress(&p_cwqkv, g_cwqkv);
    cudaGetSymbolAddress(&p_cwout, g_cwout);
    cudaGetSymbolAddress(&p_cw1, g_cw1);
    cudaGetSymbolAddress(&p_cw2, g_cw2);

    const int gsmem = (int)sizeof(GemmSmem);   // ~75 KB dynamic
    cudaFuncSetAttribute(gemm_kernel<0>, cudaFuncAttributeMaxDynamicSharedMemorySize, gsmem);
    cudaFuncSetAttribute(gemm_kernel<1>, cudaFuncAttributeMaxDynamicSharedMemorySize, gsmem);
    cudaFuncSetAttribute(gemm_kernel<2>, cudaFuncAttributeMaxDynamicSharedMemorySize, gsmem);

    // 0: all weight conversions fused
    cvt4_kernel<<<1024, 256>>>(w_qkv, w_out, w1, w2,
                               (__half*)p_cwqkv, (__half*)p_cwout,
                               (__half*)p_cw1, (__half*)p_cw2);
    // 1: LN1
    ln_kernel<<<TOK, 256>>>(x, ln1_g, ln1_b, (__half*)p_xn);
    // 2: QKV projection
    gemm_kernel<0><<<dim3(QKV3 / 128, TOK / 128), 256, gsmem>>>(
        (const __half*)p_xn, (const __half*)p_cwqkv, nullptr, nullptr, p_qkv, TOK, QKV3, EMB);
    // 3: fused attention
    flash_kernel<<<dim3(SEQ / 128, 2 * NHEAD), 256>>>();
    // 4: out projection + bias + residual(x)   <-- ncu -s 5 lands here
    gemm_kernel<2><<<dim3(EMB / 128, TOK / 128), 256, gsmem>>>(
        (const __half*)p_wavg, (const __half*)p_cwout, b_out, x, p_x2, TOK, EMB, EMB);
    // 5: LN2
    ln_kernel<<<TOK, 256>>>((const float*)p_x2, ln2_g, ln2_b, (__half*)p_xn);
    // 6: FF1 + bias + gelu
    gemm_kernel<1><<<dim3(FFDIM / 128, TOK / 128), 256, gsmem>>>(
        (const __half*)p_xn, (const __half*)p_cw1, b1, nullptr, p_h, TOK, FFDIM, EMB);
    // 7: FF2 + bias + residual
    gemm_kernel<2><<<dim3(EMB / 128, TOK / 128), 256, gsmem>>>(
        (const __half*)p_h, (const __half*)p_cw2, b2, (const float*)p_x2, d_out, TOK, EMB, FFDIM);
}